// round 8
// baseline (speedup 1.0000x reference)
#include <cuda_runtime.h>

// IntraAgg, R7: single kernel (R6's norm-precompute reverted — it cost more
// than it saved; norms are free ALU on rows already in flight).
//   - one warp per batch row, lane = float4 chunk, coalesced 512B row loads
//   - 4 groups of 8 neighbors; per group: dots in slots 0-7, norms in 8-15,
//     16-slot transpose reduction (stages 8/4/2/1 within 16-lane halves +
//     one cross-half add). pv[16] (not pv[32]) -> fewer regs, higher occ.
//   - rank-based top-ns (32 independent shfl/compares) replaces the serial
//     REDUX selection chain; tie-break by lowest index == lax.top_k.
//   - ns==10 fast path: phase-3 re-reads batched 5-wide (MLP).

#define FULLM 0xffffffffu
#define K_NEIGH 32

__global__ __launch_bounds__(256)
void intra_agg_kernel(const float* __restrict__ features,
                      const int*   __restrict__ nodes,
                      const int*   __restrict__ neighs,
                      const int*   __restrict__ nsp,   // may be null
                      float*       __restrict__ out,
                      int B)
{
    const int warp = (blockIdx.x * blockDim.x + threadIdx.x) >> 5;
    const int lane = threadIdx.x & 31;
    if (warp >= B) return;
    const int b = warp;

    int ns = (nsp != nullptr) ? __ldg(nsp) : 10;
    ns = min(max(ns, 1), K_NEIGH);

    const float4* __restrict__ f4   = reinterpret_cast<const float4*>(features);
    const int*    __restrict__ nrow = neighs + b * K_NEIGH;
    const int4*   __restrict__ n4   = reinterpret_cast<const int4*>(nrow);

    const int   node = __ldg(&nodes[b]);
    const float4 c4  = __ldg(&f4[node * 32 + lane]);

    // ---------------- Phase 1: ranking score for neighbor `lane` -----------
    float score = 0.0f;
    #pragma unroll
    for (int g = 0; g < 4; ++g) {
        const int4 qa = __ldg(&n4[g * 2]);
        const int4 qb = __ldg(&n4[g * 2 + 1]);
        const int r[8] = {qa.x, qa.y, qa.z, qa.w, qb.x, qb.y, qb.z, qb.w};
        float4 v[8];
        #pragma unroll
        for (int j = 0; j < 8; ++j)
            v[j] = __ldg(&f4[r[j] * 32 + lane]);

        float pv[16];                       // slots 0-7: dot, 8-15: |n|^2
        #pragma unroll
        for (int j = 0; j < 8; ++j) {
            pv[j]     = c4.x * v[j].x + c4.y * v[j].y
                      + c4.z * v[j].z + c4.w * v[j].w;
            pv[j + 8] = v[j].x * v[j].x + v[j].y * v[j].y
                      + v[j].z * v[j].z + v[j].w * v[j].w;
        }
        // 16-slot transpose reduce within each 16-lane half (8+4+2+1 shfl):
        // afterwards lane l's pv[0] = half-sum of slot (l & 15).
        #pragma unroll
        for (int o = 8; o >= 1; o >>= 1) {
            #pragma unroll
            for (int j = 0; j < o; ++j) {
                const float send = (lane & o) ? pv[j] : pv[j + o];
                const float recv = __shfl_xor_sync(FULLM, send, o);
                pv[j] = ((lane & o) ? pv[j + o] : pv[j]) + recv;
            }
        }
        // combine halves -> full sum of slot (lane&15) on every lane
        const float full  = pv[0] + __shfl_xor_sync(FULLM, pv[0], 16);
        // pair dot (slot s<8) with norm (slot s+8)
        const float other = __shfl_xor_sync(FULLM, full, 8);
        const float dotv  = (lane & 8) ? other : full;
        const float nrmv  = (lane & 8) ? full  : other;
        const float sc    = dotv * rsqrtf(nrmv);   // cosine rank (c-norm drops)
        if ((lane >> 3) == g) score = sc;          // neighbor g*8 + (lane&7)
    }

    // ---------------- Phase 2: rank-based top-ns ---------------------------
    unsigned u = __float_as_uint(score);
    u = (u & 0x80000000u) ? ~u : (u | 0x80000000u);   // monotonic f32 -> u32

    int cnt = 0;
    #pragma unroll
    for (int j = 0; j < 32; ++j) {
        const unsigned uj = __shfl_sync(FULLM, u, j);
        cnt += (int)((uj > u) || (uj == u && j < lane));
    }
    const unsigned sel = __ballot_sync(FULLM, cnt < ns);  // exactly ns bits

    // ---------------- Phase 3: mean of selected rows + relu ----------------
    float ax = 0.f, ay = 0.f, az = 0.f, aw = 0.f;
    if (ns == 10) {
        int kk[10];
        unsigned rem = sel;
        #pragma unroll
        for (int i = 0; i < 10; ++i) { kk[i] = __ffs(rem) - 1; rem &= rem - 1; }
        int rI[10];
        #pragma unroll
        for (int i = 0; i < 10; ++i) rI[i] = __ldg(&nrow[kk[i]]);   // L1-hot
        #pragma unroll
        for (int i0 = 0; i0 < 10; i0 += 5) {
            float4 v[5];
            #pragma unroll
            for (int i = 0; i < 5; ++i)
                v[i] = __ldg(&f4[rI[i0 + i] * 32 + lane]);
            #pragma unroll
            for (int i = 0; i < 5; ++i) {
                ax += v[i].x; ay += v[i].y; az += v[i].z; aw += v[i].w;
            }
        }
    } else {
        unsigned rem = sel;
        for (int i = 0; i < ns; ++i) {
            const int k = __ffs(rem) - 1;
            rem &= rem - 1;
            const int rI = __ldg(&nrow[k]);
            const float4 v = __ldg(&f4[rI * 32 + lane]);
            ax += v.x; ay += v.y; az += v.z; aw += v.w;
        }
    }
    const float inv = 1.0f / (float)ns;
    float4 o;
    o.x = fmaxf(ax * inv, 0.0f);
    o.y = fmaxf(ay * inv, 0.0f);
    o.z = fmaxf(az * inv, 0.0f);
    o.w = fmaxf(aw * inv, 0.0f);
    reinterpret_cast<float4*>(out)[b * 32 + lane] = o;
}

extern "C" void kernel_launch(void* const* d_in, const int* in_sizes, int n_in,
                              void* d_out, int out_size)
{
    const float* features = (const float*)d_in[0];
    const int*   nodes    = (const int*)d_in[1];
    const int*   neighs   = (const int*)d_in[2];
    const int*   nsp      = (n_in > 3) ? (const int*)d_in[3] : nullptr;

    const int B = in_sizes[1];                 // nodes element count = batch
    const int threads = 256;                   // 8 warps = 8 rows per block
    const int grid = (B + 7) / 8;

    intra_agg_kernel<<<grid, threads>>>(features, nodes, neighs, nsp,
                                        (float*)d_out, B);
}

// round 9
// speedup vs baseline: 1.5412x; 1.5412x over previous
#include <cuda_runtime.h>

// IntraAgg, R9 = R5 (best, 49.6us) + three isolated instruction/latency cuts:
//   - int4 neighbor-index loads, 32-bit address math (R6-validated: alu 43->29)
//   - rank-based top-ns (32 independent shfl/cmp) replacing the ~600-cycle
//     serial REDUX-max loop (kernel is latency-bound: no pipe >60%)
//   - phase-3 re-reads batched 5-wide (MLP on the tail chain)
// Core reduction is R5's proven form: per 16-neighbor half, dots in slots
// 0-15 / norms in 16-31, one 32-slot transpose reduction (31 shfl).

#define FULLM 0xffffffffu
#define K_NEIGH 32

__global__ __launch_bounds__(256)
void intra_agg_kernel(const float* __restrict__ features,
                      const int*   __restrict__ nodes,
                      const int*   __restrict__ neighs,
                      const int*   __restrict__ nsp,   // may be null
                      float*       __restrict__ out,
                      int B)
{
    const int warp = (blockIdx.x * blockDim.x + threadIdx.x) >> 5;
    const int lane = threadIdx.x & 31;
    if (warp >= B) return;
    const int b = warp;

    int ns = (nsp != nullptr) ? __ldg(nsp) : 10;
    ns = min(max(ns, 1), K_NEIGH);

    const float4* __restrict__ f4   = reinterpret_cast<const float4*>(features);
    const int*    __restrict__ nrow = neighs + b * K_NEIGH;
    const int4*   __restrict__ n4   = reinterpret_cast<const int4*>(nrow);

    const int   node = __ldg(&nodes[b]);
    const float4 c4  = __ldg(&f4[node * 32 + lane]);

    // ---------------- Phase 1: ranking scores, one per lane ----------------
    // Two halves of 16 neighbors. Per half, 32 reduction slots:
    //   half 0: slot j = partial dot(n_j),      slot j+16 = partial |n_j|^2
    //   half 1: slot j+16 = partial dot(n_16+j), slot j   = partial |n_16+j|^2
    // One 32-slot transpose reduction (31 shfl) leaves slot l's sum on lane l;
    // one shfl_xor(16) pairs each dot with its norm.
    float score = 0.0f;
    #pragma unroll
    for (int half = 0; half < 2; ++half) {
        const int4 qa = __ldg(&n4[half * 4 + 0]);
        const int4 qb = __ldg(&n4[half * 4 + 1]);
        const int4 qc = __ldg(&n4[half * 4 + 2]);
        const int4 qd = __ldg(&n4[half * 4 + 3]);
        const int r[16] = {qa.x, qa.y, qa.z, qa.w, qb.x, qb.y, qb.z, qb.w,
                           qc.x, qc.y, qc.z, qc.w, qd.x, qd.y, qd.z, qd.w};

        float pv[32];
        #pragma unroll
        for (int j0 = 0; j0 < 16; j0 += 8) {
            float4 v[8];
            #pragma unroll
            for (int j = 0; j < 8; ++j)
                v[j] = __ldg(&f4[r[j0 + j] * 32 + lane]);
            #pragma unroll
            for (int j = 0; j < 8; ++j) {
                const int js = j0 + j;
                const float pd = c4.x * v[j].x + c4.y * v[j].y
                               + c4.z * v[j].z + c4.w * v[j].w;
                const float pn = v[j].x * v[j].x + v[j].y * v[j].y
                               + v[j].z * v[j].z + v[j].w * v[j].w;
                pv[half ? js + 16 : js] = pd;
                pv[half ? js : js + 16] = pn;
            }
        }

        // 32-slot transpose reduction: 16+8+4+2+1 = 31 shuffles.
        #pragma unroll
        for (int o = 16; o >= 1; o >>= 1) {
            #pragma unroll
            for (int j = 0; j < o; ++j) {
                const float send = (lane & o) ? pv[j] : pv[j + o];
                const float recv = __shfl_xor_sync(FULLM, send, o);
                pv[j] = ((lane & o) ? pv[j + o] : pv[j]) + recv;
            }
        }
        const float mine  = pv[0];                       // lane l = sum(slot l)
        const float other = __shfl_xor_sync(FULLM, mine, 16);
        const float s = mine * rsqrtf(other);            // cosine rank
        const bool valid = half ? (lane >= 16) : (lane < 16);
        if (valid) score = s;     // lane k holds score of neighbor k
    }

    // ---------------- Phase 2: rank-based top-ns ---------------------------
    // cnt = #{j : u_j > u} + #{j < lane : u_j == u}; selected iff cnt < ns.
    // Lowest-index tie-break == lax.top_k; exactly ns lanes selected.
    unsigned u = __float_as_uint(score);
    u = (u & 0x80000000u) ? ~u : (u | 0x80000000u);   // monotonic f32 -> u32

    int cnt = 0;
    #pragma unroll
    for (int j = 0; j < 32; ++j) {
        const unsigned uj = __shfl_sync(FULLM, u, j);
        cnt += (int)((uj > u) || (uj == u && j < lane));
    }
    const unsigned sel = __ballot_sync(FULLM, cnt < ns);

    // ---------------- Phase 3: mean of selected rows + relu ----------------
    float ax = 0.f, ay = 0.f, az = 0.f, aw = 0.f;
    if (ns == 10) {
        int kk[10];
        unsigned rem = sel;
        #pragma unroll
        for (int i = 0; i < 10; ++i) { kk[i] = __ffs(rem) - 1; rem &= rem - 1; }
        int rI[10];
        #pragma unroll
        for (int i = 0; i < 10; ++i) rI[i] = __ldg(&nrow[kk[i]]);   // L1-hot
        #pragma unroll
        for (int i0 = 0; i0 < 10; i0 += 5) {
            float4 v[5];
            #pragma unroll
            for (int i = 0; i < 5; ++i)
                v[i] = __ldg(&f4[rI[i0 + i] * 32 + lane]);
            #pragma unroll
            for (int i = 0; i < 5; ++i) {
                ax += v[i].x; ay += v[i].y; az += v[i].z; aw += v[i].w;
            }
        }
    } else {
        unsigned rem = sel;
        for (int i = 0; i < ns; ++i) {
            const int k = __ffs(rem) - 1;
            rem &= rem - 1;
            const int rI = __ldg(&nrow[k]);
            const float4 v = __ldg(&f4[rI * 32 + lane]);
            ax += v.x; ay += v.y; az += v.z; aw += v.w;
        }
    }
    const float inv = 1.0f / (float)ns;
    float4 o;
    o.x = fmaxf(ax * inv, 0.0f);
    o.y = fmaxf(ay * inv, 0.0f);
    o.z = fmaxf(az * inv, 0.0f);
    o.w = fmaxf(aw * inv, 0.0f);
    reinterpret_cast<float4*>(out)[b * 32 + lane] = o;
}

extern "C" void kernel_launch(void* const* d_in, const int* in_sizes, int n_in,
                              void* d_out, int out_size)
{
    const float* features = (const float*)d_in[0];
    const int*   nodes    = (const int*)d_in[1];
    const int*   neighs   = (const int*)d_in[2];
    const int*   nsp      = (n_in > 3) ? (const int*)d_in[3] : nullptr;

    const int B = in_sizes[1];                 // nodes element count = batch
    const int threads = 256;                   // 8 warps = 8 rows per block
    const int grid = (B + 7) / 8;

    intra_agg_kernel<<<grid, threads>>>(features, nodes, neighs, nsp,
                                        (float*)d_out, B);
}

// round 13
// speedup vs baseline: 1.6086x; 1.0437x over previous
#include <cuda_runtime.h>

// IntraAgg, R10 = R5/R9 skeleton, minimized issue-slot count:
//   - Packed f32x2 (Blackwell) mul/fma for dot+norm partials: 8 FFMA/neighbor
//     -> 4 f32x2 ops + 2 horizontal adds. ptxas never fuses FFMA2 itself.
//   - Phase-2 selection = R5's REDUX loop (fewest instructions; R7 proved
//     instruction count dominates over ILP/occupancy for this kernel).
//   - int4 neighbor-index loads, 32-bit addressing, phase-3 re-reads batched.
// Core: per 16-neighbor half, dots in slots 0-15 / norms in 16-31, one
// 32-slot transpose reduction (31 shfl), pairing via shfl_xor(16).

#define FULLM 0xffffffffu
#define K_NEIGH 32

typedef unsigned long long u64;

__device__ __forceinline__ u64 pk2(float lo, float hi) {
    u64 r; asm("mov.b64 %0, {%1, %2};" : "=l"(r) : "f"(lo), "f"(hi)); return r;
}
__device__ __forceinline__ void upk2(float& lo, float& hi, u64 v) {
    asm("mov.b64 {%0, %1}, %2;" : "=f"(lo), "=f"(hi) : "l"(v));
}
__device__ __forceinline__ u64 mul2(u64 a, u64 b) {
    u64 d; asm("mul.rn.f32x2 %0, %1, %2;" : "=l"(d) : "l"(a), "l"(b)); return d;
}
__device__ __forceinline__ u64 fma2(u64 a, u64 b, u64 c) {
    u64 d; asm("fma.rn.f32x2 %0, %1, %2, %3;" : "=l"(d) : "l"(a), "l"(b), "l"(c)); return d;
}
__device__ __forceinline__ u64 add2(u64 a, u64 b) {
    u64 d; asm("add.rn.f32x2 %0, %1, %2;" : "=l"(d) : "l"(a), "l"(b)); return d;
}

__global__ __launch_bounds__(256)
void intra_agg_kernel(const float* __restrict__ features,
                      const int*   __restrict__ nodes,
                      const int*   __restrict__ neighs,
                      const int*   __restrict__ nsp,   // may be null
                      float*       __restrict__ out,
                      int B)
{
    const int warp = (blockIdx.x * blockDim.x + threadIdx.x) >> 5;
    const int lane = threadIdx.x & 31;
    if (warp >= B) return;
    const int b = warp;

    int ns = (nsp != nullptr) ? __ldg(nsp) : 10;
    ns = min(max(ns, 1), K_NEIGH);

    const float4* __restrict__ f4   = reinterpret_cast<const float4*>(features);
    const int*    __restrict__ nrow = neighs + b * K_NEIGH;
    const int4*   __restrict__ n4   = reinterpret_cast<const int4*>(nrow);

    const int   node = __ldg(&nodes[b]);
    const float4 c4  = __ldg(&f4[node * 32 + lane]);
    const u64 cxy = pk2(c4.x, c4.y);
    const u64 czw = pk2(c4.z, c4.w);

    // ---------------- Phase 1: ranking scores, one per lane ----------------
    float score = 0.0f;
    #pragma unroll
    for (int half = 0; half < 2; ++half) {
        const int4 qa = __ldg(&n4[half * 4 + 0]);
        const int4 qb = __ldg(&n4[half * 4 + 1]);
        const int4 qc = __ldg(&n4[half * 4 + 2]);
        const int4 qd = __ldg(&n4[half * 4 + 3]);
        const int r[16] = {qa.x, qa.y, qa.z, qa.w, qb.x, qb.y, qb.z, qb.w,
                           qc.x, qc.y, qc.z, qc.w, qd.x, qd.y, qd.z, qd.w};

        float pv[32];
        #pragma unroll
        for (int j0 = 0; j0 < 16; j0 += 8) {
            float4 v[8];
            #pragma unroll
            for (int j = 0; j < 8; ++j)
                v[j] = __ldg(&f4[r[j0 + j] * 32 + lane]);
            #pragma unroll
            for (int j = 0; j < 8; ++j) {
                const int js = j0 + j;
                const u64 vxy = pk2(v[j].x, v[j].y);   // aligned pair: ~free
                const u64 vzw = pk2(v[j].z, v[j].w);
                u64 d2 = mul2(vxy, cxy);  d2 = fma2(vzw, czw, d2);
                u64 n2 = mul2(vxy, vxy);  n2 = fma2(vzw, vzw, n2);
                float dl, dh, nl, nh;
                upk2(dl, dh, d2); upk2(nl, nh, n2);
                pv[half ? js + 16 : js] = dl + dh;     // partial dot
                pv[half ? js : js + 16] = nl + nh;     // partial |n|^2
            }
        }

        // 32-slot transpose reduction: 16+8+4+2+1 = 31 shuffles.
        #pragma unroll
        for (int o = 16; o >= 1; o >>= 1) {
            #pragma unroll
            for (int j = 0; j < o; ++j) {
                const float send = (lane & o) ? pv[j] : pv[j + o];
                const float recv = __shfl_xor_sync(FULLM, send, o);
                pv[j] = ((lane & o) ? pv[j + o] : pv[j]) + recv;
            }
        }
        const float mine  = pv[0];                       // lane l = sum(slot l)
        const float other = __shfl_xor_sync(FULLM, mine, 16);
        const float s = mine * rsqrtf(other);            // cosine rank
        const bool valid = half ? (lane >= 16) : (lane < 16);
        if (valid) score = s;     // lane k holds score of neighbor k
    }

    // ---------------- Phase 2: top-ns selection (REDUX loop, R5-proven) ----
    unsigned u = __float_as_uint(score);
    u = (u & 0x80000000u) ? ~u : (u | 0x80000000u);   // monotonic f32 -> u32

    unsigned sel = 0u;
    for (int i = 0; i < ns; ++i) {
        unsigned v   = ((sel >> lane) & 1u) ? 0u : u;
        unsigned m   = __reduce_max_sync(FULLM, v);
        unsigned bal = __ballot_sync(FULLM, v == m);
        sel |= 1u << (__ffs(bal) - 1);                // lowest index on ties
    }

    // ---------------- Phase 3: mean of selected rows + relu ----------------
    u64 axy = pk2(0.f, 0.f), azw = pk2(0.f, 0.f);
    if (ns == 10) {
        int kk[10];
        unsigned rem = sel;
        #pragma unroll
        for (int i = 0; i < 10; ++i) { kk[i] = __ffs(rem) - 1; rem &= rem - 1; }
        int rI[10];
        #pragma unroll
        for (int i = 0; i < 10; ++i) rI[i] = __ldg(&nrow[kk[i]]);   // L1-hot
        #pragma unroll
        for (int i0 = 0; i0 < 10; i0 += 5) {
            float4 v[5];
            #pragma unroll
            for (int i = 0; i < 5; ++i)
                v[i] = __ldg(&f4[rI[i0 + i] * 32 + lane]);
            #pragma unroll
            for (int i = 0; i < 5; ++i) {
                axy = add2(axy, pk2(v[i].x, v[i].y));
                azw = add2(azw, pk2(v[i].z, v[i].w));
            }
        }
    } else {
        unsigned rem = sel;
        for (int i = 0; i < ns; ++i) {
            const int k = __ffs(rem) - 1;
            rem &= rem - 1;
            const int rI = __ldg(&nrow[k]);
            const float4 v = __ldg(&f4[rI * 32 + lane]);
            axy = add2(axy, pk2(v.x, v.y));
            azw = add2(azw, pk2(v.z, v.w));
        }
    }
    float ax, ay, az, aw;
    upk2(ax, ay, axy); upk2(az, aw, azw);
    const float inv = 1.0f / (float)ns;
    float4 o;
    o.x = fmaxf(ax * inv, 0.0f);
    o.y = fmaxf(ay * inv, 0.0f);
    o.z = fmaxf(az * inv, 0.0f);
    o.w = fmaxf(aw * inv, 0.0f);
    reinterpret_cast<float4*>(out)[b * 32 + lane] = o;
}

extern "C" void kernel_launch(void* const* d_in, const int* in_sizes, int n_in,
                              void* d_out, int out_size)
{
    const float* features = (const float*)d_in[0];
    const int*   nodes    = (const int*)d_in[1];
    const int*   neighs   = (const int*)d_in[2];
    const int*   nsp      = (n_in > 3) ? (const int*)d_in[3] : nullptr;

    const int B = in_sizes[1];                 // nodes element count = batch
    const int threads = 256;                   // 8 warps = 8 rows per block
    const int grid = (B + 7) / 8;

    intra_agg_kernel<<<grid, threads>>>(features, nodes, neighs, nsp,
                                        (float*)d_out, B);
}